// round 9
// baseline (speedup 1.0000x reference)
#include <cuda_runtime.h>
#include <cuda_bf16.h>
#include <math.h>

#define NN 50000
#define EE 800000
#define OUTC 40
#define NTILE 196            // ceil(50000/256)

__device__ __align__(128) float g_scratch[29000000];

#define PACK2(dst, lo, hi) asm("mov.b64 %0, {%1, %2};" : "=l"(dst) : "f"(lo), "f"(hi))
#define UNPK2(lo, hi, v)   asm("mov.b64 {%0, %1}, %2;" : "=f"(lo), "=f"(hi) : "l"(v))
#define FMA2(acc, a, b)    asm("fma.rn.f32x2 %0, %1, %2, %0;" : "+l"(acc) : "l"(a), "l"(b))

// ======================= init: counts, flag, float stat accumulators =======
__global__ void init_kernel(int* c1, int* c2, int* flag64, float* statz) {
    int i = blockIdx.x * blockDim.x + threadIdx.x;
    if (i < NN) { c1[i] = 1; c2[i] = 0; }     // c1 starts at 1 (self-loop)
    if (i == 0) *flag64 = 1;
    if (i < 640) statz[i] = 0.f;
}

__global__ void detect_kernel(const int* __restrict__ w, int* flag64) {
    int any = 0;
    for (int i = blockIdx.x * blockDim.x + threadIdx.x; i < EE; i += gridDim.x * blockDim.x)
        any |= w[2 * i + 1];
    if (any) atomicAnd(flag64, 0);
}

// convert edge_index to int32 row/col AND histogram in one pass
__global__ void convert_hist_kernel(const int* __restrict__ w, const int* __restrict__ flag64,
                                    int* __restrict__ rowA, int* __restrict__ colA,
                                    int* c1, int* c2) {
    int e = blockIdx.x * blockDim.x + threadIdx.x;
    if (e >= EE) return;
    int r, c;
    if (*flag64) { r = w[2 * e]; c = w[2 * (EE + e)]; }
    else         { r = w[e];     c = w[EE + e]; }
    rowA[e] = r; colA[e] = c;
    atomicAdd(&c1[c], 1);
    atomicAdd(&c2[r], 1);
}

// ---- parallel 3-phase exclusive scan over two arrays (gridDim.y selects) ----
__global__ void scan_p1(const int* __restrict__ cnt1, const int* __restrict__ cnt2,
                        int* __restrict__ btot) {
    const int* cnt = blockIdx.y ? cnt2 : cnt1;
    __shared__ int sw[8];
    int idx = blockIdx.x * 256 + threadIdx.x;
    int v = (idx < NN) ? cnt[idx] : 0;
#pragma unroll
    for (int d = 16; d; d >>= 1) v += __shfl_xor_sync(0xffffffffu, v, d);
    if ((threadIdx.x & 31) == 0) sw[threadIdx.x >> 5] = v;
    __syncthreads();
    if (threadIdx.x == 0) {
        int s = 0;
#pragma unroll
        for (int i = 0; i < 8; i++) s += sw[i];
        btot[blockIdx.y * (NTILE + 1) + blockIdx.x] = s;
    }
}

__global__ void scan_p2(int* __restrict__ btot) {
    int* b = btot + blockIdx.y * (NTILE + 1);
    __shared__ int sw[8], sw2[9];
    int t = threadIdx.x, lane = t & 31, wid = t >> 5;
    int v = (t < NTILE) ? b[t] : 0;
    int inc = v;
#pragma unroll
    for (int d = 1; d < 32; d <<= 1) { int y = __shfl_up_sync(0xffffffffu, inc, d); if (lane >= d) inc += y; }
    if (lane == 31) sw[wid] = inc;
    __syncthreads();
    if (t == 0) { sw2[0] = 0; for (int i = 0; i < 8; i++) sw2[i + 1] = sw2[i] + sw[i]; }
    __syncthreads();
    int excl = sw2[wid] + inc - v;
    if (t < NTILE) b[t] = excl;
    if (t == 0) b[NTILE] = sw2[8];
}

// scan phase 3 + cursor init + self-loop placement
__global__ void scan_p3(const int* __restrict__ cnt1, const int* __restrict__ cnt2,
                        const int* __restrict__ btot,
                        int* __restrict__ off1, int* __restrict__ off2,
                        int* __restrict__ cur1, int* __restrict__ cur2, int* __restrict__ csr1) {
    const int* cnt = blockIdx.y ? cnt2 : cnt1;
    int* off = blockIdx.y ? off2 : off1;
    const int* b = btot + blockIdx.y * (NTILE + 1);
    __shared__ int sw[8], sw2[9];
    int t = threadIdx.x, lane = t & 31, wid = t >> 5;
    int idx = blockIdx.x * 256 + t;
    int v = (idx < NN) ? cnt[idx] : 0;
    int inc = v;
#pragma unroll
    for (int d = 1; d < 32; d <<= 1) { int y = __shfl_up_sync(0xffffffffu, inc, d); if (lane >= d) inc += y; }
    if (lane == 31) sw[wid] = inc;
    __syncthreads();
    if (t == 0) { sw2[0] = 0; for (int i = 0; i < 8; i++) sw2[i + 1] = sw2[i] + sw[i]; }
    __syncthreads();
    int excl = b[blockIdx.x] + sw2[wid] + inc - v;
    if (idx < NN) {
        off[idx] = excl;
        if (blockIdx.y == 0) { cur1[idx] = excl + 1; csr1[excl] = idx; }
        else                 cur2[idx] = excl;
    }
    if (blockIdx.x == 0 && t == 0) off[NN] = b[NTILE];
}

__global__ void fill_kernel(const int* __restrict__ rowA, const int* __restrict__ colA,
                            int* cur1, int* csr1,
                            int* cur2, int* csr2c, int* csr2e) {
    int e = blockIdx.x * blockDim.x + threadIdx.x;
    if (e >= EE) return;
    int r = rowA[e];
    int c = colA[e];
    int p = atomicAdd(&cur1[c], 1);
    csr1[p] = r;
    int q = atomicAdd(&cur2[r], 1);
    csr2c[q] = c;
    csr2e[q] = e;
}

// ======================= weight fusion: Wf = Wg1 @ W_res, bf = Wg1 @ b_res ==
__global__ void wfuse_kernel(const float* __restrict__ Wg1, const float* __restrict__ W_res,
                             const float* __restrict__ b_res,
                             float* __restrict__ Wf, float* __restrict__ bf) {
    __shared__ float sWg[128];
    __shared__ float red[128];
    int d = blockIdx.x, k = threadIdx.x;
    sWg[k] = Wg1[d * 128 + k];
    __syncthreads();
    float s = 0.f;
#pragma unroll 8
    for (int j = 0; j < 128; j++) s = fmaf(sWg[j], W_res[j * 128 + k], s);
    Wf[d * 128 + k] = s;
    red[k] = sWg[k] * b_res[k];
    __syncthreads();
    for (int st = 64; st; st >>= 1) { if (k < st) red[k] += red[k + st]; __syncthreads(); }
    if (k == 0) bf[d] = red[0];
}

// ======================= GEMM (K = 128 fixed, f32x2 FMA) ====================
// out[n][ocol+col] = sum_k A'[n][k] * W[wrow(col)*ldw + woff + wko(col) + k] + bias
// SPLITW merges the two edge-scorer GEMMs into one TC=128 launch.

template <int TC, bool BNIN, bool ATTN, bool STATS, bool SPLITW>
__global__ void __launch_bounds__(128)
gemm_k128(const float* __restrict__ A, const float* __restrict__ W,
          int ldw, int woff, const float* __restrict__ bias,
          float* __restrict__ out, int opitch, int ocol, int nrows,
          const float* __restrict__ bnm, const float* __restrict__ bnr,
          const float* __restrict__ bng, const float* __restrict__ bnb,
          const float* __restrict__ as, const float* __restrict__ ad,
          float* __restrict__ asrc, float* __restrict__ adst,
          float* gsum, float* gsq) {
    constexpr int CT = TC / 16;
    constexpr int PA = 68;
    constexpr int PW = TC + 4;
    __shared__ float sA[32 * PA];
    __shared__ float sW[32 * PW];
    const int tid = threadIdx.x;
    const int trow = tid >> 4;     // 0..7
    const int tcol = tid & 15;     // 0..15
    const int r0 = blockIdx.x * 64;

    unsigned long long acc2[4][CT];   // row-pairs x cols
#pragma unroll
    for (int p = 0; p < 4; p++)
#pragma unroll
        for (int j = 0; j < CT; j++) acc2[p][j] = 0ull;

    for (int kb = 0; kb < 128; kb += 32) {
        float bm = 0.f, br = 0.f, bgm = 0.f, bbt = 0.f;
        if (BNIN) {
            int kf = kb + (tid & 31);
            bm = bnm[kf]; br = bnr[kf]; bgm = bng[kf]; bbt = bnb[kf];
        }
        __syncthreads();
#pragma unroll
        for (int i = 0; i < 16; i++) {
            int idx = tid + i * 128;
            int row = idx >> 5, kk = idx & 31;
            int gr = r0 + row;
            float v = (gr < nrows) ? A[(size_t)gr * 128 + kb + kk] : 0.f;
            if (BNIN && gr < nrows) {
                float t = (v - bm) * br * bgm + bbt;
                v = (t > 0.f) ? t : expm1f(t);
            }
            sA[kk * PA + row] = v;
        }
#pragma unroll
        for (int i = 0; i < (TC * 32) / 128; i++) {
            int idx = tid + i * 128;
            int col = idx >> 5, kk = idx & 31;
            int wrow = SPLITW ? (col & 63) : col;
            int wko  = SPLITW ? ((col >> 6) * 128) : 0;
            sW[kk * PW + col] = W[(size_t)wrow * ldw + woff + wko + kb + kk];
        }
        __syncthreads();
#pragma unroll
        for (int kk = 0; kk < 32; kk++) {
            // row pairs are adjacent in sA -> direct 64-bit loads, no packing
            unsigned long long ap[4];
#pragma unroll
            for (int p = 0; p < 4; p++)
                ap[p] = *(const unsigned long long*)&sA[kk * PA + trow * 8 + 2 * p];
            float w[CT];
#pragma unroll
            for (int j = 0; j < CT; j += 4) {
                float4 wv = *(const float4*)&sW[kk * PW + tcol * CT + j];
                w[j] = wv.x; w[j + 1] = wv.y; w[j + 2] = wv.z; w[j + 3] = wv.w;
            }
            unsigned long long wd[CT];
#pragma unroll
            for (int j = 0; j < CT; j++) PACK2(wd[j], w[j], w[j]);
#pragma unroll
            for (int p = 0; p < 4; p++)
#pragma unroll
                for (int j = 0; j < CT; j++) FMA2(acc2[p][j], ap[p], wd[j]);
        }
    }
    // ---- store ----
#pragma unroll
    for (int p = 0; p < 4; p++) {
        int gr0 = r0 + trow * 8 + 2 * p;
#pragma unroll
        for (int j = 0; j < CT; j++) {
            int col = tcol * CT + j;
            float b = bias ? bias[col] : 0.f;
            float lo, hi;
            UNPK2(lo, hi, acc2[p][j]);
            if (gr0 < nrows)     out[(size_t)gr0 * opitch + ocol + col]       = lo + b;
            if (gr0 + 1 < nrows) out[(size_t)(gr0 + 1) * opitch + ocol + col] = hi + b;
        }
    }
    // ---- fused attention dots (TC=128 only) ----
    if (ATTN) {
#pragma unroll
        for (int p = 0; p < 4; p++) {
            float s1lo = 0.f, s2lo = 0.f, s1hi = 0.f, s2hi = 0.f;
#pragma unroll
            for (int j = 0; j < CT; j++) {
                int col = tcol * CT + j;
                float aS = __ldg(&as[col]), aD = __ldg(&ad[col]);
                float lo, hi;
                UNPK2(lo, hi, acc2[p][j]);
                s1lo = fmaf(lo, aS, s1lo); s2lo = fmaf(lo, aD, s2lo);
                s1hi = fmaf(hi, aS, s1hi); s2hi = fmaf(hi, aD, s2hi);
            }
            s1lo += __shfl_xor_sync(0xffffffffu, s1lo, 1);
            s2lo += __shfl_xor_sync(0xffffffffu, s2lo, 1);
            s1hi += __shfl_xor_sync(0xffffffffu, s1hi, 1);
            s2hi += __shfl_xor_sync(0xffffffffu, s2hi, 1);
            if (!(tcol & 1)) {
                int h = tcol >> 1;
                int rlo = r0 + trow * 8 + 2 * p;
                if (rlo < nrows)     { asrc[rlo * 8 + h] = s1lo;       adst[rlo * 8 + h] = s2lo; }
                if (rlo + 1 < nrows) { asrc[(rlo + 1) * 8 + h] = s1hi; adst[(rlo + 1) * 8 + h] = s2hi; }
            }
        }
    }
    // ---- fused per-feature BN statistics ----
    if (STATS) {
        __shared__ float s_s[8][TC], s_q[8][TC];
#pragma unroll
        for (int j = 0; j < CT; j++) {
            int col = tcol * CT + j;
            float b = bias ? bias[col] : 0.f;
            float ps = 0.f, pq = 0.f;
#pragma unroll
            for (int p = 0; p < 4; p++) {
                int gr0 = r0 + trow * 8 + 2 * p;
                float lo, hi;
                UNPK2(lo, hi, acc2[p][j]);
                if (gr0 < nrows)     { float v = lo + b; ps += v; pq = fmaf(v, v, pq); }
                if (gr0 + 1 < nrows) { float v = hi + b; ps += v; pq = fmaf(v, v, pq); }
            }
            s_s[trow][col] = ps;
            s_q[trow][col] = pq;
        }
        __syncthreads();
        if (tid < TC) {
            float S = 0.f, Q = 0.f;
#pragma unroll
            for (int w = 0; w < 8; w++) { S += s_s[w][tid]; Q += s_q[w][tid]; }
            atomicAdd(&gsum[tid], S);
            atomicAdd(&gsq[tid],  Q);
        }
    }
}

// ======================= GAT aggregation (online softmax + BN stats) =======
// one warp per node; unrolled x2 for memory-level parallelism

__global__ void __launch_bounds__(256)
gat_aggregate(const float* __restrict__ hfeat,
              const float* __restrict__ asrc, const float* __restrict__ adst,
              const int* __restrict__ off, const int* __restrict__ csr,
              const float* __restrict__ bg, float* __restrict__ outp,
              float* gsum, float* gsq) {
    __shared__ float s_v[8][128];
    int gw = (blockIdx.x * blockDim.x + threadIdx.x) >> 5;
    int lane = threadIdx.x & 31;
    int wib = threadIdx.x >> 5;
    int head = lane >> 2;
    float ad = adst[gw * 8 + head];
    float mm = -INFINITY, den = 0.f;
    float4 acc = make_float4(0.f, 0.f, 0.f, 0.f);
    int s0 = off[gw], s1 = off[gw + 1];
    int i = s0;
    for (; i + 1 < s1; i += 2) {
        int sa = csr[i], sb = csr[i + 1];
        float ea = asrc[sa * 8 + head] + ad;
        float eb = asrc[sb * 8 + head] + ad;
        ea = (ea >= 0.f) ? ea : 0.2f * ea;
        eb = (eb >= 0.f) ? eb : 0.2f * eb;
        float4 ha = *(const float4*)&hfeat[(size_t)sa * 128 + lane * 4];
        float4 hb = *(const float4*)&hfeat[(size_t)sb * 128 + lane * 4];
        float m2 = fmaxf(ea, eb);
        if (m2 > mm) {
            float sc = __expf(mm - m2);
            den *= sc;
            acc.x *= sc; acc.y *= sc; acc.z *= sc; acc.w *= sc;
            mm = m2;
        }
        float pa = __expf(ea - mm);
        float pb = __expf(eb - mm);
        den += pa + pb;
        acc.x = fmaf(ha.x, pa, fmaf(hb.x, pb, acc.x));
        acc.y = fmaf(ha.y, pa, fmaf(hb.y, pb, acc.y));
        acc.z = fmaf(ha.z, pa, fmaf(hb.z, pb, acc.z));
        acc.w = fmaf(ha.w, pa, fmaf(hb.w, pb, acc.w));
    }
    if (i < s1) {
        int s = csr[i];
        float e = asrc[s * 8 + head] + ad;
        e = (e >= 0.f) ? e : 0.2f * e;
        if (e > mm) {
            float sc = __expf(mm - e);
            den *= sc;
            acc.x *= sc; acc.y *= sc; acc.z *= sc; acc.w *= sc;
            mm = e;
        }
        float p = __expf(e - mm);
        den += p;
        float4 hv = *(const float4*)&hfeat[(size_t)s * 128 + lane * 4];
        acc.x = fmaf(hv.x, p, acc.x);
        acc.y = fmaf(hv.y, p, acc.y);
        acc.z = fmaf(hv.z, p, acc.z);
        acc.w = fmaf(hv.w, p, acc.w);
    }
    float inv = 1.f / (den + 1e-16f);
    float4 bgv = *(const float4*)&bg[lane * 4];
    acc.x = fmaf(acc.x, inv, bgv.x);
    acc.y = fmaf(acc.y, inv, bgv.y);
    acc.z = fmaf(acc.z, inv, bgv.z);
    acc.w = fmaf(acc.w, inv, bgv.w);
    *(float4*)&outp[(size_t)gw * 128 + lane * 4] = acc;
    *(float4*)&s_v[wib][lane * 4] = acc;
    __syncthreads();
    int t = threadIdx.x;
    if (t < 128) {
        float S = 0.f, Q = 0.f;
#pragma unroll
        for (int w = 0; w < 8; w++) { float v = s_v[w][t]; S += v; Q = fmaf(v, v, Q); }
        atomicAdd(&gsum[t], S);
        atomicAdd(&gsq[t],  Q);
    }
}

// ======================= BN finalize + BN-ELU ==============================

__global__ void bn_finalize(const float* __restrict__ gs, const float* __restrict__ gq,
                            float* mean, float* rstd, int F) {
    int f = threadIdx.x;
    if (f < F) {
        double invN = 1.0 / (double)NN;
        double mu = (double)gs[f] * invN;
        double var = (double)gq[f] * invN - mu * mu;
        if (var < 0.0) var = 0.0;
        mean[f] = (float)mu;
        rstd[f] = rsqrtf((float)var + 1e-5f);
    }
}

__global__ void bn_elu_kernel(const float* __restrict__ x, const float* __restrict__ mean,
                              const float* __restrict__ rstd, const float* __restrict__ gamma,
                              const float* __restrict__ beta, float* __restrict__ out, int total) {
    int i = (blockIdx.x * blockDim.x + threadIdx.x) * 4;
    if (i >= total) return;
    float4 v = *(const float4*)&x[i];
    int f = i & 127;
    float r[4] = {v.x, v.y, v.z, v.w};
#pragma unroll
    for (int k = 0; k < 4; k++) {
        int ff = f + k;
        float t = (r[k] - mean[ff]) * rstd[ff] * gamma[ff] + beta[ff];
        r[k] = (t > 0.f) ? t : expm1f(t);
    }
    *(float4*)&out[i] = make_float4(r[0], r[1], r[2], r[3]);
}

// ======================= Edge scorer + gumbel gate =========================

__global__ void edge_logits_kernel(const float* __restrict__ prpc,
                                   const int* __restrict__ rowA, const int* __restrict__ colA,
                                   const float* __restrict__ gumbel,
                                   const float* __restrict__ bs1,
                                   const float* __restrict__ ws2,
                                   const float* __restrict__ bs2,
                                   float* __restrict__ wout, float* __restrict__ lrout) {
    __shared__ float sw2[64];
    __shared__ float sb1[64];
    if (threadIdx.x < 64) { sw2[threadIdx.x] = ws2[threadIdx.x]; sb1[threadIdx.x] = bs1[threadIdx.x]; }
    __syncthreads();
    int ge = (blockIdx.x * blockDim.x + threadIdx.x) >> 5;
    if (ge >= EE) return;
    int lane = threadIdx.x & 31;
    int r = rowA[ge];
    int c = colA[ge];
    float p0 = prpc[(size_t)r * 128 + lane]      + prpc[(size_t)c * 128 + 64 + lane] + sb1[lane];
    float p1 = prpc[(size_t)r * 128 + 32 + lane] + prpc[(size_t)c * 128 + 96 + lane] + sb1[32 + lane];
    p0 = fmaxf(p0, 0.f);
    p1 = fmaxf(p1, 0.f);
    float part = p0 * sw2[lane] + p1 * sw2[32 + lane];
#pragma unroll
    for (int d = 16; d; d >>= 1) part += __shfl_xor_sync(0xffffffffu, part, d);
    if (lane == 0) {
        float lr = part + bs2[0];
        lrout[ge] = lr;
        float g0 = gumbel[2 * (size_t)ge];
        float g1 = gumbel[2 * (size_t)ge + 1];
        wout[ge] = (lr + g1 > g0) ? 1.f : 0.f;
    }
}

// h_sparse = h_base + segment_sum(weights * h_base[col], row), unrolled x2
__global__ void sparse_agg_kernel(const float* __restrict__ hbase,
                                  const int* __restrict__ off2,
                                  const int* __restrict__ col, const int* __restrict__ eid,
                                  const float* __restrict__ w, float* __restrict__ outp) {
    int gw = (blockIdx.x * blockDim.x + threadIdx.x) >> 5;
    if (gw >= NN) return;
    int lane = threadIdx.x & 31;
    float4 acc = *(const float4*)&hbase[(size_t)gw * 128 + lane * 4];
    int s0 = off2[gw], s1 = off2[gw + 1];
    int i = s0;
    for (; i + 1 < s1; i += 2) {
        int e0 = eid[i],  e1 = eid[i + 1];
        int c0 = col[i],  c1 = col[i + 1];
        float w0 = w[e0], w1 = w[e1];
        if (w0 != 0.f) {
            float4 h = *(const float4*)&hbase[(size_t)c0 * 128 + lane * 4];
            acc.x += h.x; acc.y += h.y; acc.z += h.z; acc.w += h.w;
        }
        if (w1 != 0.f) {
            float4 h = *(const float4*)&hbase[(size_t)c1 * 128 + lane * 4];
            acc.x += h.x; acc.y += h.y; acc.z += h.z; acc.w += h.w;
        }
    }
    if (i < s1) {
        int e = eid[i];
        if (w[e] != 0.f) {
            int c = col[i];
            float4 h = *(const float4*)&hbase[(size_t)c * 128 + lane * 4];
            acc.x += h.x; acc.y += h.y; acc.z += h.z; acc.w += h.w;
        }
    }
    *(float4*)&outp[(size_t)gw * 128 + lane * 4] = acc;
}

// ======================= Classifier head ===================================

__global__ void __launch_bounds__(256)
classifier_kernel(const float* __restrict__ cpre, const float* __restrict__ mean,
                  const float* __restrict__ rstd, const float* __restrict__ gc,
                  const float* __restrict__ bec, const float* __restrict__ Wc2,
                  const float* __restrict__ bc2, float* __restrict__ outls) {
    __shared__ float sW[64 * 64];
    __shared__ float sb[40];
    __shared__ float sc[8][64];
    for (int idx = threadIdx.x; idx < 64 * 64; idx += blockDim.x) {
        int f = idx >> 6, j = idx & 63;
        sW[idx] = (j < 40) ? Wc2[j * 64 + f] : 0.f;
    }
    if (threadIdx.x < 40) sb[threadIdx.x] = bc2[threadIdx.x];
    __syncthreads();
    int gw = (blockIdx.x * blockDim.x + threadIdx.x) >> 5;
    int lane = threadIdx.x & 31;
    int wib = threadIdx.x >> 5;
    if (gw >= NN) return;
    float v0 = cpre[(size_t)gw * 64 + lane];
    float v1 = cpre[(size_t)gw * 64 + 32 + lane];
    int f0 = lane, f1 = lane + 32;
    sc[wib][lane]      = fmaxf((v0 - mean[f0]) * rstd[f0] * gc[f0] + bec[f0], 0.f);
    sc[wib][lane + 32] = fmaxf((v1 - mean[f1]) * rstd[f1] * gc[f1] + bec[f1], 0.f);
    __syncwarp();
    float l0 = sb[lane];
    float l1 = (lane < 8) ? sb[lane + 32] : 0.f;
#pragma unroll
    for (int f = 0; f < 64; f++) {
        float cv = sc[wib][f];
        l0 = fmaf(cv, sW[f * 64 + lane], l0);
        l1 = fmaf(cv, sW[f * 64 + lane + 32], l1);
    }
    float mx = fmaxf(l0, (lane < 8) ? l1 : -INFINITY);
#pragma unroll
    for (int d = 16; d; d >>= 1) mx = fmaxf(mx, __shfl_xor_sync(0xffffffffu, mx, d));
    float s = expf(l0 - mx) + ((lane < 8) ? expf(l1 - mx) : 0.f);
#pragma unroll
    for (int d = 16; d; d >>= 1) s += __shfl_xor_sync(0xffffffffu, s, d);
    float lse = mx + logf(s);
    outls[(size_t)gw * 40 + lane] = l0 - lse;
    if (lane < 8) outls[(size_t)gw * 40 + 32 + lane] = l1 - lse;
}

// ======================= Host orchestration ================================

extern "C" void kernel_launch(void* const* d_in, const int* in_sizes, int n_in,
                              void* d_out, int out_size) {
    (void)in_sizes; (void)n_in; (void)out_size;

    float* S = nullptr;
    cudaGetSymbolAddress((void**)&S, g_scratch);

    float* bufA = S;                       // N*128
    float* bufH = S + 6400000;             // N*128
    float* bufG = S + 12800000;            // N*128
    float* bufC = S + 19200000;            // N*64
    float* asrc = S + 22400000;            // N*8
    float* adst = S + 22800000;
    float* fpar = S + 23200000;
    float* mean1 = fpar,       * rstd1 = fpar + 128;
    float* mean2 = fpar + 256, * rstd2 = fpar + 384;
    float* meanc = fpar + 512, * rstdc = fpar + 640;
    float* stat  = S + 23201024;
    float* s1s = stat,       * s1q = stat + 128;
    float* s2s = stat + 256, * s2q = stat + 384;
    float* scs = stat + 512, * scq = stat + 576;
    float* Wf   = S + 23300000;            // 128*128 fused weight
    float* bf   = Wf + 16384;              // 128 fused bias
    int* ip    = (int*)(S + 24000000);
    int* rowA  = ip;
    int* colA  = rowA + EE;
    int* off1  = colA + EE;
    int* off2  = off1 + (NN + 1);
    int* cur1  = off2 + (NN + 1);
    int* cur2  = cur1 + NN;
    int* cnt1  = cur2 + NN;
    int* cnt2  = cnt1 + NN;
    int* csr1  = cnt2 + NN;
    int* csr2c = csr1 + (EE + NN);
    int* csr2e = csr2c + EE;
    int* flag64 = csr2e + EE;
    int* btot   = flag64 + 1;

    const float* x      = (const float*)d_in[0];
    const int*   eiw    = (const int*)d_in[1];
    const float* gumbel = (const float*)d_in[2];
    const float* W_res  = (const float*)d_in[3];
    const float* b_res  = (const float*)d_in[4];
    const float* Wg1    = (const float*)d_in[5];
    const float* as1    = (const float*)d_in[6];
    const float* ad1    = (const float*)d_in[7];
    const float* bg1    = (const float*)d_in[8];
    const float* g1     = (const float*)d_in[9];
    const float* be1    = (const float*)d_in[10];
    const float* Wg2    = (const float*)d_in[11];
    const float* as2    = (const float*)d_in[12];
    const float* ad2    = (const float*)d_in[13];
    const float* bg2    = (const float*)d_in[14];
    const float* g2     = (const float*)d_in[15];
    const float* be2    = (const float*)d_in[16];
    const float* Ws1    = (const float*)d_in[17];
    const float* bs1    = (const float*)d_in[18];
    const float* Ws2    = (const float*)d_in[19];
    const float* bs2    = (const float*)d_in[20];
    const float* Wc1    = (const float*)d_in[21];
    const float* bc1    = (const float*)d_in[22];
    const float* gc     = (const float*)d_in[23];
    const float* bec    = (const float*)d_in[24];
    const float* Wc2    = (const float*)d_in[25];
    const float* bc2    = (const float*)d_in[26];

    float* out_ls = (float*)d_out;
    float* out_w  = out_ls + (size_t)NN * OUTC;
    float* out_lr = out_w + EE;

    const int NB   = (NN + 255) / 256;
    const int EB   = (EE + 255) / 256;
    const int WRPN = (NN * 32) / 256;
    const int WRPE = (EE * 32) / 256;
    const int GEMG = (NN + 63) / 64;

    // ---- fork: CSR build on side stream, GEMMs on main stream ----
    cudaStream_t s1str;
    cudaEvent_t evFork, evJoin, evBN, evElu;
    cudaStreamCreateWithFlags(&s1str, cudaStreamNonBlocking);
    cudaEventCreateWithFlags(&evFork, cudaEventDisableTiming);
    cudaEventCreateWithFlags(&evJoin, cudaEventDisableTiming);
    cudaEventCreateWithFlags(&evBN,   cudaEventDisableTiming);
    cudaEventCreateWithFlags(&evElu,  cudaEventDisableTiming);

    cudaEventRecord(evFork, 0);
    cudaStreamWaitEvent(s1str, evFork, 0);

    // side stream: CSR build chain
    init_kernel<<<NB, 256, 0, s1str>>>(cnt1, cnt2, flag64, stat);
    detect_kernel<<<256, 256, 0, s1str>>>(eiw, flag64);
    convert_hist_kernel<<<EB, 256, 0, s1str>>>(eiw, flag64, rowA, colA, cnt1, cnt2);
    scan_p1<<<dim3(NTILE, 2), 256, 0, s1str>>>(cnt1, cnt2, btot);
    scan_p2<<<dim3(1, 2), 256, 0, s1str>>>(btot);
    scan_p3<<<dim3(NTILE, 2), 256, 0, s1str>>>(cnt1, cnt2, btot, off1, off2, cur1, cur2, csr1);
    fill_kernel<<<EB, 256, 0, s1str>>>(rowA, colA, cur1, csr1, cur2, csr2c, csr2e);
    cudaEventRecord(evJoin, s1str);

    // main stream: weight fusion, then fused h1 GEMM (+attention dots)
    wfuse_kernel<<<128, 128>>>(Wg1, W_res, b_res, Wf, bf);
    gemm_k128<128, false, true, false, false><<<GEMG, 128>>>(
        x, Wf, 128, 0, bf, bufH, 128, 0, NN,
        nullptr, nullptr, nullptr, nullptr, as1, ad1, asrc, adst, nullptr, nullptr);

    // join: aggregation needs CSR + stats-zeroing from side stream
    cudaStreamWaitEvent(0, evJoin, 0);

    gat_aggregate<<<WRPN, 256>>>(bufH, asrc, adst, off1, csr1, bg1, bufG, s1s, s1q);
    bn_finalize<<<1, 128>>>(s1s, s1q, mean1, rstd1, 128);

    // GAT layer 2 (BN+ELU of layer1 fused into A-load)
    gemm_k128<128, true, true, false, false><<<GEMG, 128>>>(
        bufG, Wg2, 128, 0, nullptr, bufH, 128, 0, NN,
        mean1, rstd1, g1, be1, as2, ad2, asrc, adst, nullptr, nullptr);
    gat_aggregate<<<WRPN, 256>>>(bufH, asrc, adst, off1, csr1, bg2, bufG, s2s, s2q);
    bn_finalize<<<1, 128>>>(s2s, s2q, mean2, rstd2, 128);
    // bufG = pre-BN layer-2 activations; h_base = elu(bn2(bufG))

    // fork: bn_elu (materializes h_base into bufA) runs on side stream,
    // concurrent with the edge-scorer GEMM which applies BN+ELU in its A-load.
    cudaEventRecord(evBN, 0);
    cudaStreamWaitEvent(s1str, evBN, 0);
    bn_elu_kernel<<<(NN * 32 + 255) / 256, 256, 0, s1str>>>(
        bufG, mean2, rstd2, g2, be2, bufA, NN * 128);
    cudaEventRecord(evElu, s1str);

    // edge scorer: single merged SPLITW GEMM (pr | pc), BN+ELU fused on input
    gemm_k128<128, true, false, false, true><<<GEMG, 128>>>(
        bufG, Ws1, 256, 0, nullptr, bufH, 128, 0, NN,
        mean2, rstd2, g2, be2, nullptr, nullptr, nullptr, nullptr, nullptr, nullptr);
    edge_logits_kernel<<<WRPE, 256>>>(bufH, rowA, colA, gumbel, bs1, Ws2, bs2, out_w, out_lr);

    // sparse aggregation (needs bufA from bn_elu and out_w; writes bufG)
    cudaStreamWaitEvent(0, evElu, 0);
    sparse_agg_kernel<<<WRPN, 256>>>(bufA, off2, csr2c, csr2e, out_w, bufG);

    // classifier (BN stats fused into GEMM)
    gemm_k128<64, false, false, true, false><<<GEMG, 128>>>(
        bufG, Wc1, 128, 0, bc1, bufC, 64, 0, NN,
        nullptr, nullptr, nullptr, nullptr, nullptr, nullptr, nullptr, nullptr, scs, scq);
    bn_finalize<<<1, 64>>>(scs, scq, meanc, rstdc, 64);
    classifier_kernel<<<WRPN, 256>>>(bufC, meanc, rstdc, gc, bec, Wc2, bc2, out_ls);
}

// round 10
// speedup vs baseline: 1.0439x; 1.0439x over previous
#include <cuda_runtime.h>
#include <cuda_bf16.h>
#include <math.h>

#define NN 50000
#define EE 800000
#define OUTC 40
#define NTILE 196            // ceil(50000/256)

__device__ __align__(128) float g_scratch[29000000];

#define PACK2(dst, lo, hi) asm("mov.b64 %0, {%1, %2};" : "=l"(dst) : "f"(lo), "f"(hi))
#define UNPK2(lo, hi, v)   asm("mov.b64 {%0, %1}, %2;" : "=f"(lo), "=f"(hi) : "l"(v))
#define FMA2(acc, a, b)    asm("fma.rn.f32x2 %0, %1, %2, %0;" : "+l"(acc) : "l"(a), "l"(b))

// ======================= init: counts, flag, float stat accumulators =======
__global__ void init_kernel(int* c1, int* c2, int* flag64, float* statz) {
    int i = blockIdx.x * blockDim.x + threadIdx.x;
    if (i < NN) { c1[i] = 1; c2[i] = 0; }     // c1 starts at 1 (self-loop)
    if (i == 0) *flag64 = 1;
    if (i < 640) statz[i] = 0.f;
}

__global__ void detect_kernel(const int* __restrict__ w, int* flag64) {
    int any = 0;
    for (int i = blockIdx.x * blockDim.x + threadIdx.x; i < EE; i += gridDim.x * blockDim.x)
        any |= w[2 * i + 1];
    if (any) atomicAnd(flag64, 0);
}

// convert edge_index to int32 row/col AND histogram in one pass
__global__ void convert_hist_kernel(const int* __restrict__ w, const int* __restrict__ flag64,
                                    int* __restrict__ rowA, int* __restrict__ colA,
                                    int* c1, int* c2) {
    int e = blockIdx.x * blockDim.x + threadIdx.x;
    if (e >= EE) return;
    int r, c;
    if (*flag64) { r = w[2 * e]; c = w[2 * (EE + e)]; }
    else         { r = w[e];     c = w[EE + e]; }
    rowA[e] = r; colA[e] = c;
    atomicAdd(&c1[c], 1);
    atomicAdd(&c2[r], 1);
}

// ---- parallel 3-phase exclusive scan over two arrays (gridDim.y selects) ----
__global__ void scan_p1(const int* __restrict__ cnt1, const int* __restrict__ cnt2,
                        int* __restrict__ btot) {
    const int* cnt = blockIdx.y ? cnt2 : cnt1;
    __shared__ int sw[8];
    int idx = blockIdx.x * 256 + threadIdx.x;
    int v = (idx < NN) ? cnt[idx] : 0;
#pragma unroll
    for (int d = 16; d; d >>= 1) v += __shfl_xor_sync(0xffffffffu, v, d);
    if ((threadIdx.x & 31) == 0) sw[threadIdx.x >> 5] = v;
    __syncthreads();
    if (threadIdx.x == 0) {
        int s = 0;
#pragma unroll
        for (int i = 0; i < 8; i++) s += sw[i];
        btot[blockIdx.y * (NTILE + 1) + blockIdx.x] = s;
    }
}

__global__ void scan_p2(int* __restrict__ btot) {
    int* b = btot + blockIdx.y * (NTILE + 1);
    __shared__ int sw[8], sw2[9];
    int t = threadIdx.x, lane = t & 31, wid = t >> 5;
    int v = (t < NTILE) ? b[t] : 0;
    int inc = v;
#pragma unroll
    for (int d = 1; d < 32; d <<= 1) { int y = __shfl_up_sync(0xffffffffu, inc, d); if (lane >= d) inc += y; }
    if (lane == 31) sw[wid] = inc;
    __syncthreads();
    if (t == 0) { sw2[0] = 0; for (int i = 0; i < 8; i++) sw2[i + 1] = sw2[i] + sw[i]; }
    __syncthreads();
    int excl = sw2[wid] + inc - v;
    if (t < NTILE) b[t] = excl;
    if (t == 0) b[NTILE] = sw2[8];
}

// scan phase 3 + cursor init + self-loop placement
__global__ void scan_p3(const int* __restrict__ cnt1, const int* __restrict__ cnt2,
                        const int* __restrict__ btot,
                        int* __restrict__ off1, int* __restrict__ off2,
                        int* __restrict__ cur1, int* __restrict__ cur2, int* __restrict__ csr1) {
    const int* cnt = blockIdx.y ? cnt2 : cnt1;
    int* off = blockIdx.y ? off2 : off1;
    const int* b = btot + blockIdx.y * (NTILE + 1);
    __shared__ int sw[8], sw2[9];
    int t = threadIdx.x, lane = t & 31, wid = t >> 5;
    int idx = blockIdx.x * 256 + t;
    int v = (idx < NN) ? cnt[idx] : 0;
    int inc = v;
#pragma unroll
    for (int d = 1; d < 32; d <<= 1) { int y = __shfl_up_sync(0xffffffffu, inc, d); if (lane >= d) inc += y; }
    if (lane == 31) sw[wid] = inc;
    __syncthreads();
    if (t == 0) { sw2[0] = 0; for (int i = 0; i < 8; i++) sw2[i + 1] = sw2[i] + sw[i]; }
    __syncthreads();
    int excl = b[blockIdx.x] + sw2[wid] + inc - v;
    if (idx < NN) {
        off[idx] = excl;
        if (blockIdx.y == 0) { cur1[idx] = excl + 1; csr1[excl] = idx; }
        else                 cur2[idx] = excl;
    }
    if (blockIdx.x == 0 && t == 0) off[NN] = b[NTILE];
}

__global__ void fill_kernel(const int* __restrict__ rowA, const int* __restrict__ colA,
                            int* cur1, int* csr1,
                            int* cur2, int* csr2c, int* csr2e) {
    int e = blockIdx.x * blockDim.x + threadIdx.x;
    if (e >= EE) return;
    int r = rowA[e];
    int c = colA[e];
    int p = atomicAdd(&cur1[c], 1);
    csr1[p] = r;
    int q = atomicAdd(&cur2[r], 1);
    csr2c[q] = c;
    csr2e[q] = e;
}

// ======================= weight fusion: Wf = Wg1 @ W_res, bf = Wg1 @ b_res ==
__global__ void wfuse_kernel(const float* __restrict__ Wg1, const float* __restrict__ W_res,
                             const float* __restrict__ b_res,
                             float* __restrict__ Wf, float* __restrict__ bf) {
    __shared__ float sWg[128];
    __shared__ float red[128];
    int d = blockIdx.x, k = threadIdx.x;
    sWg[k] = Wg1[d * 128 + k];
    __syncthreads();
    float s = 0.f;
#pragma unroll 8
    for (int j = 0; j < 128; j++) s = fmaf(sWg[j], W_res[j * 128 + k], s);
    Wf[d * 128 + k] = s;
    red[k] = sWg[k] * b_res[k];
    __syncthreads();
    for (int st = 64; st; st >>= 1) { if (k < st) red[k] += red[k + st]; __syncthreads(); }
    if (k == 0) bf[d] = red[0];
}

// ======================= GEMM (K = 128 fixed, f32x2 FMA) ====================
// out[n][ocol+col] = sum_k A'[n][k] * W[wrow(col)*ldw + woff + wko(col) + k] + bias
// SPLITW merges the two edge-scorer GEMMs into one TC=128 launch.

template <int TC, bool BNIN, bool ATTN, bool STATS, bool SPLITW>
__global__ void __launch_bounds__(128, 4)
gemm_k128(const float* __restrict__ A, const float* __restrict__ W,
          int ldw, int woff, const float* __restrict__ bias,
          float* __restrict__ out, int opitch, int ocol, int nrows,
          const float* __restrict__ bnm, const float* __restrict__ bnr,
          const float* __restrict__ bng, const float* __restrict__ bnb,
          const float* __restrict__ as, const float* __restrict__ ad,
          float* __restrict__ asrc, float* __restrict__ adst,
          float* gsum, float* gsq) {
    constexpr int CT = TC / 16;
    constexpr int PA = 68;
    constexpr int PW = TC + 4;
    __shared__ float sA[32 * PA];
    __shared__ float sW[32 * PW];
    const int tid = threadIdx.x;
    const int trow = tid >> 4;     // 0..7
    const int tcol = tid & 15;     // 0..15
    const int r0 = blockIdx.x * 64;

    unsigned long long acc2[4][CT];   // row-pairs x cols
#pragma unroll
    for (int p = 0; p < 4; p++)
#pragma unroll
        for (int j = 0; j < CT; j++) acc2[p][j] = 0ull;

    for (int kb = 0; kb < 128; kb += 32) {
        float bm = 0.f, br = 0.f, bgm = 0.f, bbt = 0.f;
        if (BNIN) {
            int kf = kb + (tid & 31);
            bm = bnm[kf]; br = bnr[kf]; bgm = bng[kf]; bbt = bnb[kf];
        }
        __syncthreads();
#pragma unroll
        for (int i = 0; i < 16; i++) {
            int idx = tid + i * 128;
            int row = idx >> 5, kk = idx & 31;
            int gr = r0 + row;
            float v = (gr < nrows) ? A[(size_t)gr * 128 + kb + kk] : 0.f;
            if (BNIN && gr < nrows) {
                float t = (v - bm) * br * bgm + bbt;
                v = (t > 0.f) ? t : expm1f(t);
            }
            sA[kk * PA + row] = v;
        }
#pragma unroll
        for (int i = 0; i < (TC * 32) / 128; i++) {
            int idx = tid + i * 128;
            int col = idx >> 5, kk = idx & 31;
            int wrow = SPLITW ? (col & 63) : col;
            int wko  = SPLITW ? ((col >> 6) * 128) : 0;
            sW[kk * PW + col] = W[(size_t)wrow * ldw + woff + wko + kb + kk];
        }
        __syncthreads();
#pragma unroll
        for (int kk = 0; kk < 32; kk++) {
            // row pairs are adjacent in sA -> direct 64-bit loads, no packing
            unsigned long long ap[4];
#pragma unroll
            for (int p = 0; p < 4; p++)
                ap[p] = *(const unsigned long long*)&sA[kk * PA + trow * 8 + 2 * p];
            float w[CT];
#pragma unroll
            for (int j = 0; j < CT; j += 4) {
                float4 wv = *(const float4*)&sW[kk * PW + tcol * CT + j];
                w[j] = wv.x; w[j + 1] = wv.y; w[j + 2] = wv.z; w[j + 3] = wv.w;
            }
            unsigned long long wd[CT];
#pragma unroll
            for (int j = 0; j < CT; j++) PACK2(wd[j], w[j], w[j]);
#pragma unroll
            for (int p = 0; p < 4; p++)
#pragma unroll
                for (int j = 0; j < CT; j++) FMA2(acc2[p][j], ap[p], wd[j]);
        }
    }
    // ---- store ----
#pragma unroll
    for (int p = 0; p < 4; p++) {
        int gr0 = r0 + trow * 8 + 2 * p;
#pragma unroll
        for (int j = 0; j < CT; j++) {
            int col = tcol * CT + j;
            float b = bias ? bias[col] : 0.f;
            float lo, hi;
            UNPK2(lo, hi, acc2[p][j]);
            if (gr0 < nrows)     out[(size_t)gr0 * opitch + ocol + col]       = lo + b;
            if (gr0 + 1 < nrows) out[(size_t)(gr0 + 1) * opitch + ocol + col] = hi + b;
        }
    }
    // ---- fused attention dots (TC=128 only) ----
    if (ATTN) {
#pragma unroll
        for (int p = 0; p < 4; p++) {
            float s1lo = 0.f, s2lo = 0.f, s1hi = 0.f, s2hi = 0.f;
#pragma unroll
            for (int j = 0; j < CT; j++) {
                int col = tcol * CT + j;
                float aS = __ldg(&as[col]), aD = __ldg(&ad[col]);
                float lo, hi;
                UNPK2(lo, hi, acc2[p][j]);
                s1lo = fmaf(lo, aS, s1lo); s2lo = fmaf(lo, aD, s2lo);
                s1hi = fmaf(hi, aS, s1hi); s2hi = fmaf(hi, aD, s2hi);
            }
            s1lo += __shfl_xor_sync(0xffffffffu, s1lo, 1);
            s2lo += __shfl_xor_sync(0xffffffffu, s2lo, 1);
            s1hi += __shfl_xor_sync(0xffffffffu, s1hi, 1);
            s2hi += __shfl_xor_sync(0xffffffffu, s2hi, 1);
            if (!(tcol & 1)) {
                int h = tcol >> 1;
                int rlo = r0 + trow * 8 + 2 * p;
                if (rlo < nrows)     { asrc[rlo * 8 + h] = s1lo;       adst[rlo * 8 + h] = s2lo; }
                if (rlo + 1 < nrows) { asrc[(rlo + 1) * 8 + h] = s1hi; adst[(rlo + 1) * 8 + h] = s2hi; }
            }
        }
    }
    // ---- fused per-feature BN statistics ----
    if (STATS) {
        __shared__ float s_s[8][TC], s_q[8][TC];
#pragma unroll
        for (int j = 0; j < CT; j++) {
            int col = tcol * CT + j;
            float b = bias ? bias[col] : 0.f;
            float ps = 0.f, pq = 0.f;
#pragma unroll
            for (int p = 0; p < 4; p++) {
                int gr0 = r0 + trow * 8 + 2 * p;
                float lo, hi;
                UNPK2(lo, hi, acc2[p][j]);
                if (gr0 < nrows)     { float v = lo + b; ps += v; pq = fmaf(v, v, pq); }
                if (gr0 + 1 < nrows) { float v = hi + b; ps += v; pq = fmaf(v, v, pq); }
            }
            s_s[trow][col] = ps;
            s_q[trow][col] = pq;
        }
        __syncthreads();
        if (tid < TC) {
            float S = 0.f, Q = 0.f;
#pragma unroll
            for (int w = 0; w < 8; w++) { S += s_s[w][tid]; Q += s_q[w][tid]; }
            atomicAdd(&gsum[tid], S);
            atomicAdd(&gsq[tid],  Q);
        }
    }
}

// ======================= GAT aggregation (online softmax + BN stats) =======
// one warp per node; unrolled x2 for memory-level parallelism

__global__ void __launch_bounds__(256)
gat_aggregate(const float* __restrict__ hfeat,
              const float* __restrict__ asrc, const float* __restrict__ adst,
              const int* __restrict__ off, const int* __restrict__ csr,
              const float* __restrict__ bg, float* __restrict__ outp,
              float* gsum, float* gsq) {
    __shared__ float s_v[8][128];
    int gw = (blockIdx.x * blockDim.x + threadIdx.x) >> 5;
    int lane = threadIdx.x & 31;
    int wib = threadIdx.x >> 5;
    int head = lane >> 2;
    float ad = adst[gw * 8 + head];
    float mm = -INFINITY, den = 0.f;
    float4 acc = make_float4(0.f, 0.f, 0.f, 0.f);
    int s0 = off[gw], s1 = off[gw + 1];
    int i = s0;
    for (; i + 1 < s1; i += 2) {
        int sa = csr[i], sb = csr[i + 1];
        float ea = asrc[sa * 8 + head] + ad;
        float eb = asrc[sb * 8 + head] + ad;
        ea = (ea >= 0.f) ? ea : 0.2f * ea;
        eb = (eb >= 0.f) ? eb : 0.2f * eb;
        float4 ha = *(const float4*)&hfeat[(size_t)sa * 128 + lane * 4];
        float4 hb = *(const float4*)&hfeat[(size_t)sb * 128 + lane * 4];
        float m2 = fmaxf(ea, eb);
        if (m2 > mm) {
            float sc = __expf(mm - m2);
            den *= sc;
            acc.x *= sc; acc.y *= sc; acc.z *= sc; acc.w *= sc;
            mm = m2;
        }
        float pa = __expf(ea - mm);
        float pb = __expf(eb - mm);
        den += pa + pb;
        acc.x = fmaf(ha.x, pa, fmaf(hb.x, pb, acc.x));
        acc.y = fmaf(ha.y, pa, fmaf(hb.y, pb, acc.y));
        acc.z = fmaf(ha.z, pa, fmaf(hb.z, pb, acc.z));
        acc.w = fmaf(ha.w, pa, fmaf(hb.w, pb, acc.w));
    }
    if (i < s1) {
        int s = csr[i];
        float e = asrc[s * 8 + head] + ad;
        e = (e >= 0.f) ? e : 0.2f * e;
        if (e > mm) {
            float sc = __expf(mm - e);
            den *= sc;
            acc.x *= sc; acc.y *= sc; acc.z *= sc; acc.w *= sc;
            mm = e;
        }
        float p = __expf(e - mm);
        den += p;
        float4 hv = *(const float4*)&hfeat[(size_t)s * 128 + lane * 4];
        acc.x = fmaf(hv.x, p, acc.x);
        acc.y = fmaf(hv.y, p, acc.y);
        acc.z = fmaf(hv.z, p, acc.z);
        acc.w = fmaf(hv.w, p, acc.w);
    }
    float inv = 1.f / (den + 1e-16f);
    float4 bgv = *(const float4*)&bg[lane * 4];
    acc.x = fmaf(acc.x, inv, bgv.x);
    acc.y = fmaf(acc.y, inv, bgv.y);
    acc.z = fmaf(acc.z, inv, bgv.z);
    acc.w = fmaf(acc.w, inv, bgv.w);
    *(float4*)&outp[(size_t)gw * 128 + lane * 4] = acc;
    *(float4*)&s_v[wib][lane * 4] = acc;
    __syncthreads();
    int t = threadIdx.x;
    if (t < 128) {
        float S = 0.f, Q = 0.f;
#pragma unroll
        for (int w = 0; w < 8; w++) { float v = s_v[w][t]; S += v; Q = fmaf(v, v, Q); }
        atomicAdd(&gsum[t], S);
        atomicAdd(&gsq[t],  Q);
    }
}

// ======================= BN finalize + BN-ELU ==============================

__global__ void bn_finalize(const float* __restrict__ gs, const float* __restrict__ gq,
                            float* mean, float* rstd, int F) {
    int f = threadIdx.x;
    if (f < F) {
        double invN = 1.0 / (double)NN;
        double mu = (double)gs[f] * invN;
        double var = (double)gq[f] * invN - mu * mu;
        if (var < 0.0) var = 0.0;
        mean[f] = (float)mu;
        rstd[f] = rsqrtf((float)var + 1e-5f);
    }
}

__global__ void bn_elu_kernel(const float* __restrict__ x, const float* __restrict__ mean,
                              const float* __restrict__ rstd, const float* __restrict__ gamma,
                              const float* __restrict__ beta, float* __restrict__ out, int total) {
    int i = (blockIdx.x * blockDim.x + threadIdx.x) * 4;
    if (i >= total) return;
    float4 v = *(const float4*)&x[i];
    int f = i & 127;
    float r[4] = {v.x, v.y, v.z, v.w};
#pragma unroll
    for (int k = 0; k < 4; k++) {
        int ff = f + k;
        float t = (r[k] - mean[ff]) * rstd[ff] * gamma[ff] + beta[ff];
        r[k] = (t > 0.f) ? t : expm1f(t);
    }
    *(float4*)&out[i] = make_float4(r[0], r[1], r[2], r[3]);
}

// ======================= Edge scorer + gumbel gate =========================

__global__ void edge_logits_kernel(const float* __restrict__ prpc,
                                   const int* __restrict__ rowA, const int* __restrict__ colA,
                                   const float* __restrict__ gumbel,
                                   const float* __restrict__ bs1,
                                   const float* __restrict__ ws2,
                                   const float* __restrict__ bs2,
                                   float* __restrict__ wout, float* __restrict__ lrout) {
    __shared__ float sw2[64];
    __shared__ float sb1[64];
    if (threadIdx.x < 64) { sw2[threadIdx.x] = ws2[threadIdx.x]; sb1[threadIdx.x] = bs1[threadIdx.x]; }
    __syncthreads();
    int ge = (blockIdx.x * blockDim.x + threadIdx.x) >> 5;
    if (ge >= EE) return;
    int lane = threadIdx.x & 31;
    int r = rowA[ge];
    int c = colA[ge];
    float p0 = prpc[(size_t)r * 128 + lane]      + prpc[(size_t)c * 128 + 64 + lane] + sb1[lane];
    float p1 = prpc[(size_t)r * 128 + 32 + lane] + prpc[(size_t)c * 128 + 96 + lane] + sb1[32 + lane];
    p0 = fmaxf(p0, 0.f);
    p1 = fmaxf(p1, 0.f);
    float part = p0 * sw2[lane] + p1 * sw2[32 + lane];
#pragma unroll
    for (int d = 16; d; d >>= 1) part += __shfl_xor_sync(0xffffffffu, part, d);
    if (lane == 0) {
        float lr = part + bs2[0];
        lrout[ge] = lr;
        float g0 = gumbel[2 * (size_t)ge];
        float g1 = gumbel[2 * (size_t)ge + 1];
        wout[ge] = (lr + g1 > g0) ? 1.f : 0.f;
    }
}

// h_sparse = h_base + segment_sum(weights * h_base[col], row), unrolled x2
__global__ void sparse_agg_kernel(const float* __restrict__ hbase,
                                  const int* __restrict__ off2,
                                  const int* __restrict__ col, const int* __restrict__ eid,
                                  const float* __restrict__ w, float* __restrict__ outp) {
    int gw = (blockIdx.x * blockDim.x + threadIdx.x) >> 5;
    if (gw >= NN) return;
    int lane = threadIdx.x & 31;
    float4 acc = *(const float4*)&hbase[(size_t)gw * 128 + lane * 4];
    int s0 = off2[gw], s1 = off2[gw + 1];
    int i = s0;
    for (; i + 1 < s1; i += 2) {
        int e0 = eid[i],  e1 = eid[i + 1];
        int c0 = col[i],  c1 = col[i + 1];
        float w0 = w[e0], w1 = w[e1];
        if (w0 != 0.f) {
            float4 h = *(const float4*)&hbase[(size_t)c0 * 128 + lane * 4];
            acc.x += h.x; acc.y += h.y; acc.z += h.z; acc.w += h.w;
        }
        if (w1 != 0.f) {
            float4 h = *(const float4*)&hbase[(size_t)c1 * 128 + lane * 4];
            acc.x += h.x; acc.y += h.y; acc.z += h.z; acc.w += h.w;
        }
    }
    if (i < s1) {
        int e = eid[i];
        if (w[e] != 0.f) {
            int c = col[i];
            float4 h = *(const float4*)&hbase[(size_t)c * 128 + lane * 4];
            acc.x += h.x; acc.y += h.y; acc.z += h.z; acc.w += h.w;
        }
    }
    *(float4*)&outp[(size_t)gw * 128 + lane * 4] = acc;
}

// ======================= Classifier head ===================================

__global__ void __launch_bounds__(256)
classifier_kernel(const float* __restrict__ cpre, const float* __restrict__ mean,
                  const float* __restrict__ rstd, const float* __restrict__ gc,
                  const float* __restrict__ bec, const float* __restrict__ Wc2,
                  const float* __restrict__ bc2, float* __restrict__ outls) {
    __shared__ float sW[64 * 64];
    __shared__ float sb[40];
    __shared__ float sc[8][64];
    for (int idx = threadIdx.x; idx < 64 * 64; idx += blockDim.x) {
        int f = idx >> 6, j = idx & 63;
        sW[idx] = (j < 40) ? Wc2[j * 64 + f] : 0.f;
    }
    if (threadIdx.x < 40) sb[threadIdx.x] = bc2[threadIdx.x];
    __syncthreads();
    int gw = (blockIdx.x * blockDim.x + threadIdx.x) >> 5;
    int lane = threadIdx.x & 31;
    int wib = threadIdx.x >> 5;
    if (gw >= NN) return;
    float v0 = cpre[(size_t)gw * 64 + lane];
    float v1 = cpre[(size_t)gw * 64 + 32 + lane];
    int f0 = lane, f1 = lane + 32;
    sc[wib][lane]      = fmaxf((v0 - mean[f0]) * rstd[f0] * gc[f0] + bec[f0], 0.f);
    sc[wib][lane + 32] = fmaxf((v1 - mean[f1]) * rstd[f1] * gc[f1] + bec[f1], 0.f);
    __syncwarp();
    float l0 = sb[lane];
    float l1 = (lane < 8) ? sb[lane + 32] : 0.f;
#pragma unroll
    for (int f = 0; f < 64; f++) {
        float cv = sc[wib][f];
        l0 = fmaf(cv, sW[f * 64 + lane], l0);
        l1 = fmaf(cv, sW[f * 64 + lane + 32], l1);
    }
    float mx = fmaxf(l0, (lane < 8) ? l1 : -INFINITY);
#pragma unroll
    for (int d = 16; d; d >>= 1) mx = fmaxf(mx, __shfl_xor_sync(0xffffffffu, mx, d));
    float s = expf(l0 - mx) + ((lane < 8) ? expf(l1 - mx) : 0.f);
#pragma unroll
    for (int d = 16; d; d >>= 1) s += __shfl_xor_sync(0xffffffffu, s, d);
    float lse = mx + logf(s);
    outls[(size_t)gw * 40 + lane] = l0 - lse;
    if (lane < 8) outls[(size_t)gw * 40 + 32 + lane] = l1 - lse;
}

// ======================= Host orchestration ================================

extern "C" void kernel_launch(void* const* d_in, const int* in_sizes, int n_in,
                              void* d_out, int out_size) {
    (void)in_sizes; (void)n_in; (void)out_size;

    float* S = nullptr;
    cudaGetSymbolAddress((void**)&S, g_scratch);

    float* bufA = S;                       // N*128
    float* bufH = S + 6400000;             // N*128
    float* bufG = S + 12800000;            // N*128
    float* bufC = S + 19200000;            // N*64
    float* asrc = S + 22400000;            // N*8
    float* adst = S + 22800000;
    float* fpar = S + 23200000;
    float* mean1 = fpar,       * rstd1 = fpar + 128;
    float* mean2 = fpar + 256, * rstd2 = fpar + 384;
    float* meanc = fpar + 512, * rstdc = fpar + 640;
    float* stat  = S + 23201024;
    float* s1s = stat,       * s1q = stat + 128;
    float* s2s = stat + 256, * s2q = stat + 384;
    float* scs = stat + 512, * scq = stat + 576;
    float* Wf   = S + 23300000;            // 128*128 fused weight
    float* bf   = Wf + 16384;              // 128 fused bias
    int* ip    = (int*)(S + 24000000);
    int* rowA  = ip;
    int* colA  = rowA + EE;
    int* off1  = colA + EE;
    int* off2  = off1 + (NN + 1);
    int* cur1  = off2 + (NN + 1);
    int* cur2  = cur1 + NN;
    int* cnt1  = cur2 + NN;
    int* cnt2  = cnt1 + NN;
    int* csr1  = cnt2 + NN;
    int* csr2c = csr1 + (EE + NN);
    int* csr2e = csr2c + EE;
    int* flag64 = csr2e + EE;
    int* btot   = flag64 + 1;

    const float* x      = (const float*)d_in[0];
    const int*   eiw    = (const int*)d_in[1];
    const float* gumbel = (const float*)d_in[2];
    const float* W_res  = (const float*)d_in[3];
    const float* b_res  = (const float*)d_in[4];
    const float* Wg1    = (const float*)d_in[5];
    const float* as1    = (const float*)d_in[6];
    const float* ad1    = (const float*)d_in[7];
    const float* bg1    = (const float*)d_in[8];
    const float* g1     = (const float*)d_in[9];
    const float* be1    = (const float*)d_in[10];
    const float* Wg2    = (const float*)d_in[11];
    const float* as2    = (const float*)d_in[12];
    const float* ad2    = (const float*)d_in[13];
    const float* bg2    = (const float*)d_in[14];
    const float* g2     = (const float*)d_in[15];
    const float* be2    = (const float*)d_in[16];
    const float* Ws1    = (const float*)d_in[17];
    const float* bs1    = (const float*)d_in[18];
    const float* Ws2    = (const float*)d_in[19];
    const float* bs2    = (const float*)d_in[20];
    const float* Wc1    = (const float*)d_in[21];
    const float* bc1    = (const float*)d_in[22];
    const float* gc     = (const float*)d_in[23];
    const float* bec    = (const float*)d_in[24];
    const float* Wc2    = (const float*)d_in[25];
    const float* bc2    = (const float*)d_in[26];

    float* out_ls = (float*)d_out;
    float* out_w  = out_ls + (size_t)NN * OUTC;
    float* out_lr = out_w + EE;

    const int NB   = (NN + 255) / 256;
    const int EB   = (EE + 255) / 256;
    const int WRPN = (NN * 32) / 256;
    const int WRPE = (EE * 32) / 256;
    const int GEMG = (NN + 63) / 64;

    // ---- fork: CSR build on side stream, GEMMs on main stream ----
    cudaStream_t s1str;
    cudaEvent_t evFork, evJoin;
    cudaStreamCreateWithFlags(&s1str, cudaStreamNonBlocking);
    cudaEventCreateWithFlags(&evFork, cudaEventDisableTiming);
    cudaEventCreateWithFlags(&evJoin, cudaEventDisableTiming);

    cudaEventRecord(evFork, 0);
    cudaStreamWaitEvent(s1str, evFork, 0);

    // side stream: CSR build chain
    init_kernel<<<NB, 256, 0, s1str>>>(cnt1, cnt2, flag64, stat);
    detect_kernel<<<256, 256, 0, s1str>>>(eiw, flag64);
    convert_hist_kernel<<<EB, 256, 0, s1str>>>(eiw, flag64, rowA, colA, cnt1, cnt2);
    scan_p1<<<dim3(NTILE, 2), 256, 0, s1str>>>(cnt1, cnt2, btot);
    scan_p2<<<dim3(1, 2), 256, 0, s1str>>>(btot);
    scan_p3<<<dim3(NTILE, 2), 256, 0, s1str>>>(cnt1, cnt2, btot, off1, off2, cur1, cur2, csr1);
    fill_kernel<<<EB, 256, 0, s1str>>>(rowA, colA, cur1, csr1, cur2, csr2c, csr2e);
    cudaEventRecord(evJoin, s1str);

    // main stream: weight fusion, then fused h1 GEMM (+attention dots)
    wfuse_kernel<<<128, 128>>>(Wg1, W_res, b_res, Wf, bf);
    gemm_k128<128, false, true, false, false><<<GEMG, 128>>>(
        x, Wf, 128, 0, bf, bufH, 128, 0, NN,
        nullptr, nullptr, nullptr, nullptr, as1, ad1, asrc, adst, nullptr, nullptr);

    // join: aggregation needs CSR + stats-zeroing from side stream
    cudaStreamWaitEvent(0, evJoin, 0);

    gat_aggregate<<<WRPN, 256>>>(bufH, asrc, adst, off1, csr1, bg1, bufG, s1s, s1q);
    bn_finalize<<<1, 128>>>(s1s, s1q, mean1, rstd1, 128);

    // GAT layer 2 (BN+ELU of layer1 fused into A-load)
    gemm_k128<128, true, true, false, false><<<GEMG, 128>>>(
        bufG, Wg2, 128, 0, nullptr, bufH, 128, 0, NN,
        mean1, rstd1, g1, be1, as2, ad2, asrc, adst, nullptr, nullptr);
    gat_aggregate<<<WRPN, 256>>>(bufH, asrc, adst, off1, csr1, bg2, bufG, s2s, s2q);
    bn_finalize<<<1, 128>>>(s2s, s2q, mean2, rstd2, 128);
    bn_elu_kernel<<<(NN * 32 + 255) / 256, 256>>>(bufG, mean2, rstd2, g2, be2, bufA, NN * 128);
    // bufA = h_base

    // edge scorer: single merged SPLITW GEMM (pr | pc)
    gemm_k128<128, false, false, false, true><<<GEMG, 128>>>(
        bufA, Ws1, 256, 0, nullptr, bufH, 128, 0, NN,
        nullptr, nullptr, nullptr, nullptr, nullptr, nullptr, nullptr, nullptr, nullptr, nullptr);
    edge_logits_kernel<<<WRPE, 256>>>(bufH, rowA, colA, gumbel, bs1, Ws2, bs2, out_w, out_lr);

    // sparse aggregation
    sparse_agg_kernel<<<WRPN, 256>>>(bufA, off2, csr2c, csr2e, out_w, bufG);

    // classifier (BN stats fused into GEMM)
    gemm_k128<64, false, false, true, false><<<GEMG, 128>>>(
        bufG, Wc1, 128, 0, bc1, bufC, 64, 0, NN,
        nullptr, nullptr, nullptr, nullptr, nullptr, nullptr, nullptr, nullptr, scs, scq);
    bn_finalize<<<1, 64>>>(scs, scq, meanc, rstdc, 64);
    classifier_kernel<<<WRPN, 256>>>(bufC, meanc, rstdc, gc, bec, Wc2, bc2, out_ls);
}